// round 8
// baseline (speedup 1.0000x reference)
#include <cuda_runtime.h>
#include <math.h>
#include <stdint.h>

// Problem constants
#define NB   2
#define TT   1024
#define DD   1024
#define HH   16
#define DHH  64
#define WW   64
#define WIN  129

// GEMM dims
#define GM 2048
#define GN 1024
#define GK 1024
// Tiling
#define BM 128
#define BN 128
#define BK 32
#define SROW 36
#define NITER (GK / BK)
#define GEMM_STAGES 3
#define STAGE_FLOATS (BM * SROW)                       // 4608
#define SMEM_BYTES (GEMM_STAGES * 2 * STAGE_FLOATS * 4) // 110592

// Attention tiling: CTA = 32 t-rows, window union 160
#define AR   32
#define AU   160
#define AQS  66
#define AKS  66
#define AVS  68
#define APS  164
#define SM_Q   0
#define SM_K   2112
#define SM_V   12672
#define SM_RED 23552          // [32][33]
#define SM_MAX 24608
#define SM_INV 24640
#define ATT_SMEM_BYTES (24672 * 4)   // 98688

// Scratch (device globals: allocation-free per harness rules)
__device__ float g_q[NB * TT * DD];
__device__ float g_k[NB * TT * DD];
__device__ float g_v[NB * TT * DD];
__device__ float g_attn[NB * TT * DD];     // tf32-rounded by attn kernel
__device__ float g_xc[GM * GK];            // tf32-rounded x
__device__ float g_wqc[GN * GK];
__device__ float g_wkc[GN * GK];
__device__ float g_wvc[GN * GK];
__device__ float g_woc[GN * GK];

__device__ __forceinline__ float to_tf32(float x) {
    float r;
    asm("cvt.rna.tf32.f32 %0, %1;" : "=f"(r) : "f"(x));
    return r;
}

__device__ __forceinline__ uint32_t s2u(const void* p) {
    uint32_t a;
    asm("{ .reg .u64 t; cvta.to.shared.u64 t, %1; cvt.u32.u64 %0, t; }"
        : "=r"(a) : "l"(p));
    return a;
}

__device__ __forceinline__ void cp_async16(uint32_t dst, const void* src) {
    asm volatile("cp.async.cg.shared.global [%0], [%1], 16;"
                 :: "r"(dst), "l"(src));
}
__device__ __forceinline__ void cp_commit() {
    asm volatile("cp.async.commit_group;");
}
template <int N>
__device__ __forceinline__ void cp_wait() {
    asm volatile("cp.async.wait_group %0;" :: "n"(N));
}

__device__ __forceinline__ void mma_16x8x8_tf32(float* d, const uint32_t* a,
                                                const uint32_t* b) {
    asm volatile(
        "mma.sync.aligned.m16n8k8.row.col.f32.tf32.tf32.f32 "
        "{%0,%1,%2,%3}, {%4,%5,%6,%7}, {%8,%9}, {%0,%1,%2,%3};"
        : "+f"(d[0]), "+f"(d[1]), "+f"(d[2]), "+f"(d[3])
        : "r"(a[0]), "r"(a[1]), "r"(a[2]), "r"(a[3]),
          "r"(b[0]), "r"(b[1]));
}

// ---------------------------------------------------------------------------
// Pre-round x and all weights to tf32 (RNA) into global scratch.
// ---------------------------------------------------------------------------
__global__ __launch_bounds__(256) void preconv_kernel(
    const float* __restrict__ x,  const float* __restrict__ wq,
    const float* __restrict__ wk, const float* __restrict__ wv,
    const float* __restrict__ wo)
{
    int i = blockIdx.x * blockDim.x + threadIdx.x;   // float4 index
    const float* src; float* dst; int off;
    if (i < 524288)       { src = x;  dst = g_xc;  off = i; }
    else if (i < 786432)  { src = wq; dst = g_wqc; off = i - 524288; }
    else if (i < 1048576) { src = wk; dst = g_wkc; off = i - 786432; }
    else if (i < 1310720) { src = wv; dst = g_wvc; off = i - 1048576; }
    else                  { src = wo; dst = g_woc; off = i - 1310720; }
    float4 v = ((const float4*)src)[off];
    v.x = to_tf32(v.x); v.y = to_tf32(v.y);
    v.z = to_tf32(v.z); v.w = to_tf32(v.w);
    ((float4*)dst)[off] = v;
}

// ---------------------------------------------------------------------------
// tf32 mma.sync GEMM: C = A @ B^T + bias. Inputs pre-rounded to tf32.
// cp.async 3-stage pipeline + fragment double-buffer. 256 thr, 128x128, BK=32.
// ---------------------------------------------------------------------------
__device__ __forceinline__ void gemm_tc_body(
    const float* __restrict__ A, const float* __restrict__ B,
    const float* __restrict__ bias, float* __restrict__ C)
{
    extern __shared__ float smem[];
    float* Asm = smem;                                  // [3][4608]
    float* Bsm = smem + GEMM_STAGES * STAGE_FLOATS;

    const int tid  = threadIdx.x;
    const int lane = tid & 31;
    const int wid  = tid >> 5;
    const int wm   = wid >> 2;
    const int wn   = wid & 3;
    const int row0 = blockIdx.y * BM;
    const int col0 = blockIdx.x * BN;
    const int lrow = tid >> 3;
    const int lq   = tid & 7;
    const int c    = lane & 3;
    const int r4   = lane >> 2;

    const uint32_t sA = s2u(Asm);
    const uint32_t sB = s2u(Bsm);

    float acc[4][4][4];
#pragma unroll
    for (int m = 0; m < 4; ++m)
#pragma unroll
        for (int n = 0; n < 4; ++n)
#pragma unroll
            for (int e = 0; e < 4; ++e) acc[m][n][e] = 0.f;

#define ISSUE_STAGE(I)                                                        \
    do {                                                                      \
        int st = (I) % GEMM_STAGES;                                           \
        uint32_t da = sA + (uint32_t)(st * STAGE_FLOATS) * 4;                 \
        uint32_t db = sB + (uint32_t)(st * STAGE_FLOATS) * 4;                 \
        const float* Ag = A + (size_t)(row0 + lrow) * GK + (I) * BK + lq * 4; \
        const float* Bg = B + (size_t)(col0 + lrow) * GK + (I) * BK + lq * 4; \
        _Pragma("unroll")                                                     \
        for (int p = 0; p < 4; ++p) {                                         \
            uint32_t o = (uint32_t)(((p * 32 + lrow) * SROW + lq * 4) * 4);   \
            cp_async16(da + o, Ag + (size_t)p * 32 * GK);                     \
            cp_async16(db + o, Bg + (size_t)p * 32 * GK);                     \
        }                                                                     \
        cp_commit();                                                          \
    } while (0)

    ISSUE_STAGE(0);
    ISSUE_STAGE(1);

    for (int i = 0; i < NITER; ++i) {
        if (i == NITER - 1) cp_wait<0>(); else cp_wait<1>();
        __syncthreads();
        if (i + 2 < NITER) ISSUE_STAGE(i + 2);

        const float* Ab = Asm + (i % GEMM_STAGES) * STAGE_FLOATS;
        const float* Bb = Bsm + (i % GEMM_STAGES) * STAGE_FLOATS;
        const uint32_t* Au = (const uint32_t*)(Ab + (wm * 64 + r4) * SROW + c);
        const uint32_t* Bu = (const uint32_t*)(Bb + (wn * 32 + r4) * SROW + c);

        uint32_t af[2][4][4], bf[2][4][2];
#pragma unroll
        for (int m = 0; m < 4; ++m) {
            af[0][m][0] = Au[(m * 16 + 0) * SROW + 0];
            af[0][m][1] = Au[(m * 16 + 8) * SROW + 0];
            af[0][m][2] = Au[(m * 16 + 0) * SROW + 4];
            af[0][m][3] = Au[(m * 16 + 8) * SROW + 4];
        }
#pragma unroll
        for (int n = 0; n < 4; ++n) {
            bf[0][n][0] = Bu[n * 8 * SROW + 0];
            bf[0][n][1] = Bu[n * 8 * SROW + 4];
        }

#pragma unroll
        for (int kk = 0; kk < 4; ++kk) {
            const int cur = kk & 1;
            if (kk < 3) {
                const int ko = (kk + 1) * 8;
#pragma unroll
                for (int m = 0; m < 4; ++m) {
                    af[cur ^ 1][m][0] = Au[(m * 16 + 0) * SROW + ko + 0];
                    af[cur ^ 1][m][1] = Au[(m * 16 + 8) * SROW + ko + 0];
                    af[cur ^ 1][m][2] = Au[(m * 16 + 0) * SROW + ko + 4];
                    af[cur ^ 1][m][3] = Au[(m * 16 + 8) * SROW + ko + 4];
                }
#pragma unroll
                for (int n = 0; n < 4; ++n) {
                    bf[cur ^ 1][n][0] = Bu[n * 8 * SROW + ko + 0];
                    bf[cur ^ 1][n][1] = Bu[n * 8 * SROW + ko + 4];
                }
            }
#pragma unroll
            for (int m = 0; m < 4; ++m)
#pragma unroll
                for (int n = 0; n < 4; ++n)
                    mma_16x8x8_tf32(acc[m][n], af[cur][m], bf[cur][n]);
        }
    }
#undef ISSUE_STAGE

#pragma unroll
    for (int m = 0; m < 4; ++m) {
#pragma unroll
        for (int h = 0; h < 2; ++h) {
            const int grow = row0 + wm * 64 + m * 16 + r4 + 8 * h;
            float* crow = C + (size_t)grow * GN;
#pragma unroll
            for (int n = 0; n < 4; ++n) {
                const int gcol = col0 + wn * 32 + n * 8 + 2 * c;
                float2 o;
                o.x = acc[m][n][2 * h + 0] + __ldg(&bias[gcol + 0]);
                o.y = acc[m][n][2 * h + 1] + __ldg(&bias[gcol + 1]);
                *(float2*)(crow + gcol) = o;
            }
        }
    }
}

__global__ __launch_bounds__(256, 2) void gemm_qkv_tc(
    const float* __restrict__ bq, const float* __restrict__ bk,
    const float* __restrict__ bv)
{
    const float* B; const float* bias; float* C;
    if (blockIdx.z == 0)      { B = g_wqc; bias = bq; C = g_q; }
    else if (blockIdx.z == 1) { B = g_wkc; bias = bk; C = g_k; }
    else                      { B = g_wvc; bias = bv; C = g_v; }
    gemm_tc_body(g_xc, B, bias, C);
}

__global__ __launch_bounds__(256, 2) void gemm_out_tc(
    const float* __restrict__ bo, float* __restrict__ out)
{
    gemm_tc_body(g_attn, g_woc, bo, out);
}

// ---------------------------------------------------------------------------
// Tiled windowed attention (fp32). CTA = 32 t-rows; union 160 positions.
// smem: Q[32][66] | K[160][66] (reused as P[32][164]) | V[160][68] | red[32][33]
// ---------------------------------------------------------------------------
__global__ __launch_bounds__(256) void attn_tile_kernel()
{
    extern __shared__ float sm[];
    float* Qs   = sm + SM_Q;
    float* Ks   = sm + SM_K;
    float* Vs   = sm + SM_V;
    float* red  = sm + SM_RED;
    float* rmax = sm + SM_MAX;
    float* rinv = sm + SM_INV;

    const int tid = threadIdx.x;
    const int t0  = blockIdx.x * AR;
    const int nh  = blockIdx.y;
    const int h   = nh & (HH - 1);
    const int n   = nh >> 4;
    const size_t base = (size_t)n * TT * DD + (size_t)h * DHH;

    // ---- loads ----
    for (int idx = tid; idx < AR * 16; idx += 256) {
        int r = idx >> 4, cc = (idx & 15) << 2;
        float4 v = *(const float4*)(g_q + base + (size_t)(t0 + r) * DD + cc);
        float* dst = Qs + r * AQS + cc;
        ((float2*)dst)[0] = make_float2(v.x * 0.125f, v.y * 0.125f);
        ((float2*)dst)[1] = make_float2(v.z * 0.125f, v.w * 0.125f);
    }
    for (int idx = tid; idx < AU * 16; idx += 256) {
        int r = idx >> 4, cc = (idx & 15) << 2;
        int pos = min(max(t0 - 64 + r, 0), TT - 1);
        float4 kv = *(const float4*)(g_k + base + (size_t)pos * DD + cc);
        float* kd = Ks + r * AKS + cc;
        ((float2*)kd)[0] = make_float2(kv.x, kv.y);
        ((float2*)kd)[1] = make_float2(kv.z, kv.w);
        float4 vv = *(const float4*)(g_v + base + (size_t)pos * DD + cc);
        *(float4*)(Vs + r * AVS + cc) = vv;
    }
    __syncthreads();

    const int lane = tid & 31, wid = tid >> 5;
    const int lm = lane >> 2, ln = lane & 3;     // lanes 8(M) x 4(N)
    const int colb = wid * 20 + ln * 5;          // 5 cols per thread

    // ---- phase 1: S = Q @ K^T  (rows lm*4+i, cols colb+j) ----
    float acc[4][5];
#pragma unroll
    for (int i = 0; i < 4; ++i)
#pragma unroll
        for (int j = 0; j < 5; ++j) acc[i][j] = 0.f;

    const float* Qp = Qs + (lm * 4) * AQS;
    const float* Kp = Ks + colb * AKS;
    for (int k2 = 0; k2 < 32; ++k2) {
        float2 a[4], b[5];
#pragma unroll
        for (int i = 0; i < 4; ++i)
            a[i] = *(const float2*)(Qp + i * AQS + 2 * k2);
#pragma unroll
        for (int j = 0; j < 5; ++j)
            b[j] = *(const float2*)(Kp + j * AKS + 2 * k2);
#pragma unroll
        for (int i = 0; i < 4; ++i)
#pragma unroll
            for (int j = 0; j < 5; ++j)
                acc[i][j] += a[i].x * b[j].x + a[i].y * b[j].y;
    }

    // ---- phase 2: mask + 2-pass softmax ----
    const int lob = 64 - t0;
    const int hib = 1087 - t0;
#pragma unroll
    for (int i = 0; i < 4; ++i) {
        int row = lm * 4 + i;
        int lo = max(row, lob), hi = min(row + 128, hib);
        float m = -1e30f;
#pragma unroll
        for (int j = 0; j < 5; ++j) {
            int cc = colb + j;
            if (cc < lo || cc > hi) acc[i][j] = -1e30f;
            m = fmaxf(m, acc[i][j]);
        }
        red[row * 33 + wid * 4 + ln] = m;
    }
    __syncthreads();
    if (tid < AR) {
        float m = red[tid * 33];
#pragma unroll
        for (int p = 1; p < 32; ++p) m = fmaxf(m, red[tid * 33 + p]);
        rmax[tid] = m;
    }
    __syncthreads();

    float* Ps = Ks;    // K region dead; safe: all warps passed the sync above
#pragma unroll
    for (int i = 0; i < 4; ++i) {
        int row = lm * 4 + i;
        float m = rmax[row];
        float s = 0.f;
        float* pd = Ps + row * APS + colb;
#pragma unroll
        for (int j = 0; j < 5; ++j) {
            float e = __expf(acc[i][j] - m);
            s += e;
            pd[j] = e;
        }
        red[row * 33 + wid * 4 + ln] = s;
    }
    __syncthreads();
    if (tid < AR) {
        float s = 0.f;
#pragma unroll
        for (int p = 0; p < 32; ++p) s += red[tid * 33 + p];
        rinv[tid] = 1.0f / s;
    }
    __syncthreads();

    // ---- phase 3: out = P @ V ----
    const int prow = (wid << 2) + (lane >> 3);   // 1 row per thread
    const int pcol = (lane & 7) * 8;             // 8 dh cols per thread
    float pv[8];
#pragma unroll
    for (int j = 0; j < 8; ++j) pv[j] = 0.f;

    const float* Pp = Ps + prow * APS;
    const float* Vp = Vs + pcol;
#pragma unroll 4
    for (int k = 0; k < AU; ++k) {
        float p = Pp[k];
        float4 v0 = *(const float4*)(Vp + k * AVS);
        float4 v1 = *(const float4*)(Vp + k * AVS + 4);
        pv[0] += p * v0.x; pv[1] += p * v0.y;
        pv[2] += p * v0.z; pv[3] += p * v0.w;
        pv[4] += p * v1.x; pv[5] += p * v1.y;
        pv[6] += p * v1.z; pv[7] += p * v1.w;
    }

    const float inv = rinv[prow];
    float* op = g_attn + base + (size_t)(t0 + prow) * DD + pcol;
    float4 o0, o1;
    o0.x = to_tf32(pv[0] * inv); o0.y = to_tf32(pv[1] * inv);
    o0.z = to_tf32(pv[2] * inv); o0.w = to_tf32(pv[3] * inv);
    o1.x = to_tf32(pv[4] * inv); o1.y = to_tf32(pv[5] * inv);
    o1.z = to_tf32(pv[6] * inv); o1.w = to_tf32(pv[7] * inv);
    *(float4*)(op + 0) = o0;
    *(float4*)(op + 4) = o1;
}

// ---------------- launch ----------------
extern "C" void kernel_launch(void* const* d_in, const int* in_sizes, int n_in,
                              void* d_out, int out_size)
{
    const float* x  = (const float*)d_in[0];
    const float* wq = (const float*)d_in[1];
    const float* bq = (const float*)d_in[2];
    const float* wk = (const float*)d_in[3];
    const float* bk = (const float*)d_in[4];
    const float* wv = (const float*)d_in[5];
    const float* bv = (const float*)d_in[6];
    const float* wo = (const float*)d_in[7];
    const float* bo = (const float*)d_in[8];

    cudaFuncSetAttribute(gemm_qkv_tc,
                         cudaFuncAttributeMaxDynamicSharedMemorySize, SMEM_BYTES);
    cudaFuncSetAttribute(gemm_out_tc,
                         cudaFuncAttributeMaxDynamicSharedMemorySize, SMEM_BYTES);
    cudaFuncSetAttribute(attn_tile_kernel,
                         cudaFuncAttributeMaxDynamicSharedMemorySize, ATT_SMEM_BYTES);

    preconv_kernel<<<6144, 256>>>(x, wq, wk, wv, wo);

    dim3 gq(GN / BN, GM / BM, 3);
    gemm_qkv_tc<<<gq, 256, SMEM_BYTES>>>(bq, bk, bv);

    attn_tile_kernel<<<dim3(TT / AR, NB * HH), 256, ATT_SMEM_BYTES>>>();

    dim3 go(GN / BN, GM / BM);
    gemm_out_tc<<<go, 256, SMEM_BYTES>>>(bo, (float*)d_out);
}

// round 9
// speedup vs baseline: 1.0021x; 1.0021x over previous
#include <cuda_runtime.h>
#include <math.h>
#include <stdint.h>

// Problem constants
#define NB   2
#define TT   1024
#define DD   1024
#define HH   16
#define DHH  64
#define WW   64
#define WIN  129

// GEMM dims
#define GM 2048
#define GN 1024
#define GK 1024
// Tiling
#define BM 128
#define BN 128
#define BK 32
#define SROW 36
#define NITER (GK / BK)
#define GEMM_STAGES 2
#define STAGE_FLOATS (BM * SROW)                        // 4608
#define SMEM_BYTES (GEMM_STAGES * 2 * STAGE_FLOATS * 4) // 73728 -> 2 CTAs/SM

// Attention tiling: CTA = 32 t-rows, window union 160
#define AR   32
#define AU   160
#define AQS  66
#define AKS  66
#define AVS  68
#define APS  164
#define SM_Q   0
#define SM_K   2112
#define SM_V   12672
#define SM_RED 23552          // [32][33]
#define SM_MAX 24608
#define SM_INV 24640
#define ATT_SMEM_BYTES (24672 * 4)   // 98688

// Scratch (device globals: allocation-free per harness rules)
__device__ float g_q[NB * TT * DD];
__device__ float g_k[NB * TT * DD];
__device__ float g_v[NB * TT * DD];
__device__ float g_attn[NB * TT * DD];     // tf32-rounded by attn kernel
__device__ float g_xc[GM * GK];            // tf32-rounded x
__device__ float g_wqc[GN * GK];
__device__ float g_wkc[GN * GK];
__device__ float g_wvc[GN * GK];
__device__ float g_woc[GN * GK];

__device__ __forceinline__ float to_tf32(float x) {
    float r;
    asm("cvt.rna.tf32.f32 %0, %1;" : "=f"(r) : "f"(x));
    return r;
}

__device__ __forceinline__ uint32_t s2u(const void* p) {
    uint32_t a;
    asm("{ .reg .u64 t; cvta.to.shared.u64 t, %1; cvt.u32.u64 %0, t; }"
        : "=r"(a) : "l"(p));
    return a;
}

__device__ __forceinline__ void cp_async16(uint32_t dst, const void* src) {
    asm volatile("cp.async.cg.shared.global [%0], [%1], 16;"
                 :: "r"(dst), "l"(src));
}
__device__ __forceinline__ void cp_commit() {
    asm volatile("cp.async.commit_group;");
}
template <int N>
__device__ __forceinline__ void cp_wait() {
    asm volatile("cp.async.wait_group %0;" :: "n"(N));
}

__device__ __forceinline__ void mma_16x8x8_tf32(float* d, const uint32_t* a,
                                                const uint32_t* b) {
    asm volatile(
        "mma.sync.aligned.m16n8k8.row.col.f32.tf32.tf32.f32 "
        "{%0,%1,%2,%3}, {%4,%5,%6,%7}, {%8,%9}, {%0,%1,%2,%3};"
        : "+f"(d[0]), "+f"(d[1]), "+f"(d[2]), "+f"(d[3])
        : "r"(a[0]), "r"(a[1]), "r"(a[2]), "r"(a[3]),
          "r"(b[0]), "r"(b[1]));
}

// ---------------------------------------------------------------------------
// Pre-round x and all weights to tf32 (RNA) into global scratch.
// ---------------------------------------------------------------------------
__global__ __launch_bounds__(256) void preconv_kernel(
    const float* __restrict__ x,  const float* __restrict__ wq,
    const float* __restrict__ wk, const float* __restrict__ wv,
    const float* __restrict__ wo)
{
    int i = blockIdx.x * blockDim.x + threadIdx.x;   // float4 index
    const float* src; float* dst; int off;
    if (i < 524288)       { src = x;  dst = g_xc;  off = i; }
    else if (i < 786432)  { src = wq; dst = g_wqc; off = i - 524288; }
    else if (i < 1048576) { src = wk; dst = g_wkc; off = i - 786432; }
    else if (i < 1310720) { src = wv; dst = g_wvc; off = i - 1048576; }
    else                  { src = wo; dst = g_woc; off = i - 1310720; }
    float4 v = ((const float4*)src)[off];
    v.x = to_tf32(v.x); v.y = to_tf32(v.y);
    v.z = to_tf32(v.z); v.w = to_tf32(v.w);
    ((float4*)dst)[off] = v;
}

// ---------------------------------------------------------------------------
// tf32 mma.sync GEMM: C = A @ B^T + bias. Inputs pre-rounded to tf32.
// cp.async 2-stage pipeline + fragment double-buffer. 256 thr, 128x128, BK=32.
// 73.7 KB smem -> 2 CTAs/SM for cross-CTA latency hiding.
// ---------------------------------------------------------------------------
__device__ __forceinline__ void gemm_tc_body(
    const float* __restrict__ A, const float* __restrict__ B,
    const float* __restrict__ bias, float* __restrict__ C)
{
    extern __shared__ float smem[];
    float* Asm = smem;                                  // [2][4608]
    float* Bsm = smem + GEMM_STAGES * STAGE_FLOATS;

    const int tid  = threadIdx.x;
    const int lane = tid & 31;
    const int wid  = tid >> 5;
    const int wm   = wid >> 2;
    const int wn   = wid & 3;
    const int row0 = blockIdx.y * BM;
    const int col0 = blockIdx.x * BN;
    const int lrow = tid >> 3;
    const int lq   = tid & 7;
    const int c    = lane & 3;
    const int r4   = lane >> 2;

    const uint32_t sA = s2u(Asm);
    const uint32_t sB = s2u(Bsm);

    float acc[4][4][4];
#pragma unroll
    for (int m = 0; m < 4; ++m)
#pragma unroll
        for (int n = 0; n < 4; ++n)
#pragma unroll
            for (int e = 0; e < 4; ++e) acc[m][n][e] = 0.f;

#define ISSUE_STAGE(I)                                                        \
    do {                                                                      \
        int st = (I) & 1;                                                     \
        uint32_t da = sA + (uint32_t)(st * STAGE_FLOATS) * 4;                 \
        uint32_t db = sB + (uint32_t)(st * STAGE_FLOATS) * 4;                 \
        const float* Ag = A + (size_t)(row0 + lrow) * GK + (I) * BK + lq * 4; \
        const float* Bg = B + (size_t)(col0 + lrow) * GK + (I) * BK + lq * 4; \
        _Pragma("unroll")                                                     \
        for (int p = 0; p < 4; ++p) {                                         \
            uint32_t o = (uint32_t)(((p * 32 + lrow) * SROW + lq * 4) * 4);   \
            cp_async16(da + o, Ag + (size_t)p * 32 * GK);                     \
            cp_async16(db + o, Bg + (size_t)p * 32 * GK);                     \
        }                                                                     \
        cp_commit();                                                          \
    } while (0)

    ISSUE_STAGE(0);

    for (int i = 0; i < NITER; ++i) {
        // issue next stage into the other buffer (its readers finished at the
        // trailing __syncthreads of iteration i-1)
        if (i + 1 < NITER) { ISSUE_STAGE(i + 1); cp_wait<1>(); }
        else               { cp_wait<0>(); }
        __syncthreads();

        const float* Ab = Asm + (i & 1) * STAGE_FLOATS;
        const float* Bb = Bsm + (i & 1) * STAGE_FLOATS;
        const uint32_t* Au = (const uint32_t*)(Ab + (wm * 64 + r4) * SROW + c);
        const uint32_t* Bu = (const uint32_t*)(Bb + (wn * 32 + r4) * SROW + c);

        uint32_t af[2][4][4], bf[2][4][2];
#pragma unroll
        for (int m = 0; m < 4; ++m) {
            af[0][m][0] = Au[(m * 16 + 0) * SROW + 0];
            af[0][m][1] = Au[(m * 16 + 8) * SROW + 0];
            af[0][m][2] = Au[(m * 16 + 0) * SROW + 4];
            af[0][m][3] = Au[(m * 16 + 8) * SROW + 4];
        }
#pragma unroll
        for (int n = 0; n < 4; ++n) {
            bf[0][n][0] = Bu[n * 8 * SROW + 0];
            bf[0][n][1] = Bu[n * 8 * SROW + 4];
        }

#pragma unroll
        for (int kk = 0; kk < 4; ++kk) {
            const int cur = kk & 1;
            if (kk < 3) {
                const int ko = (kk + 1) * 8;
#pragma unroll
                for (int m = 0; m < 4; ++m) {
                    af[cur ^ 1][m][0] = Au[(m * 16 + 0) * SROW + ko + 0];
                    af[cur ^ 1][m][1] = Au[(m * 16 + 8) * SROW + ko + 0];
                    af[cur ^ 1][m][2] = Au[(m * 16 + 0) * SROW + ko + 4];
                    af[cur ^ 1][m][3] = Au[(m * 16 + 8) * SROW + ko + 4];
                }
#pragma unroll
                for (int n = 0; n < 4; ++n) {
                    bf[cur ^ 1][n][0] = Bu[n * 8 * SROW + ko + 0];
                    bf[cur ^ 1][n][1] = Bu[n * 8 * SROW + ko + 4];
                }
            }
#pragma unroll
            for (int m = 0; m < 4; ++m)
#pragma unroll
                for (int n = 0; n < 4; ++n)
                    mma_16x8x8_tf32(acc[m][n], af[cur][m], bf[cur][n]);
        }
        __syncthreads();   // protect buffer (i&1) before iter i+1 issues into it
    }
#undef ISSUE_STAGE

#pragma unroll
    for (int m = 0; m < 4; ++m) {
#pragma unroll
        for (int h = 0; h < 2; ++h) {
            const int grow = row0 + wm * 64 + m * 16 + r4 + 8 * h;
            float* crow = C + (size_t)grow * GN;
#pragma unroll
            for (int n = 0; n < 4; ++n) {
                const int gcol = col0 + wn * 32 + n * 8 + 2 * c;
                float2 o;
                o.x = acc[m][n][2 * h + 0] + __ldg(&bias[gcol + 0]);
                o.y = acc[m][n][2 * h + 1] + __ldg(&bias[gcol + 1]);
                *(float2*)(crow + gcol) = o;
            }
        }
    }
}

__global__ __launch_bounds__(256, 2) void gemm_qkv_tc(
    const float* __restrict__ bq, const float* __restrict__ bk,
    const float* __restrict__ bv)
{
    const float* B; const float* bias; float* C;
    if (blockIdx.z == 0)      { B = g_wqc; bias = bq; C = g_q; }
    else if (blockIdx.z == 1) { B = g_wkc; bias = bk; C = g_k; }
    else                      { B = g_wvc; bias = bv; C = g_v; }
    gemm_tc_body(g_xc, B, bias, C);
}

__global__ __launch_bounds__(256, 2) void gemm_out_tc(
    const float* __restrict__ bo, float* __restrict__ out)
{
    gemm_tc_body(g_attn, g_woc, bo, out);
}

// ---------------------------------------------------------------------------
// Tiled windowed attention (fp32). CTA = 32 t-rows; union 160 positions.
// smem: Q[32][66] | K[160][66] (reused as P[32][164]) | V[160][68] | red[32][33]
// ---------------------------------------------------------------------------
__global__ __launch_bounds__(256) void attn_tile_kernel()
{
    extern __shared__ float sm[];
    float* Qs   = sm + SM_Q;
    float* Ks   = sm + SM_K;
    float* Vs   = sm + SM_V;
    float* red  = sm + SM_RED;
    float* rmax = sm + SM_MAX;
    float* rinv = sm + SM_INV;

    const int tid = threadIdx.x;
    const int t0  = blockIdx.x * AR;
    const int nh  = blockIdx.y;
    const int h   = nh & (HH - 1);
    const int n   = nh >> 4;
    const size_t base = (size_t)n * TT * DD + (size_t)h * DHH;

    // ---- loads ----
    for (int idx = tid; idx < AR * 16; idx += 256) {
        int r = idx >> 4, cc = (idx & 15) << 2;
        float4 v = *(const float4*)(g_q + base + (size_t)(t0 + r) * DD + cc);
        float* dst = Qs + r * AQS + cc;
        ((float2*)dst)[0] = make_float2(v.x * 0.125f, v.y * 0.125f);
        ((float2*)dst)[1] = make_float2(v.z * 0.125f, v.w * 0.125f);
    }
    for (int idx = tid; idx < AU * 16; idx += 256) {
        int r = idx >> 4, cc = (idx & 15) << 2;
        int pos = min(max(t0 - 64 + r, 0), TT - 1);
        float4 kv = *(const float4*)(g_k + base + (size_t)pos * DD + cc);
        float* kd = Ks + r * AKS + cc;
        ((float2*)kd)[0] = make_float2(kv.x, kv.y);
        ((float2*)kd)[1] = make_float2(kv.z, kv.w);
        float4 vv = *(const float4*)(g_v + base + (size_t)pos * DD + cc);
        *(float4*)(Vs + r * AVS + cc) = vv;
    }
    __syncthreads();

    const int lane = tid & 31, wid = tid >> 5;
    const int lm = lane >> 2, ln = lane & 3;     // lanes 8(M) x 4(N)
    const int colb = wid * 20 + ln * 5;          // 5 cols per thread

    // ---- phase 1: S = Q @ K^T  (rows lm*4+i, cols colb+j) ----
    float acc[4][5];
#pragma unroll
    for (int i = 0; i < 4; ++i)
#pragma unroll
        for (int j = 0; j < 5; ++j) acc[i][j] = 0.f;

    const float* Qp = Qs + (lm * 4) * AQS;
    const float* Kp = Ks + colb * AKS;
    for (int k2 = 0; k2 < 32; ++k2) {
        float2 a[4], b[5];
#pragma unroll
        for (int i = 0; i < 4; ++i)
            a[i] = *(const float2*)(Qp + i * AQS + 2 * k2);
#pragma unroll
        for (int j = 0; j < 5; ++j)
            b[j] = *(const float2*)(Kp + j * AKS + 2 * k2);
#pragma unroll
        for (int i = 0; i < 4; ++i)
#pragma unroll
            for (int j = 0; j < 5; ++j)
                acc[i][j] += a[i].x * b[j].x + a[i].y * b[j].y;
    }

    // ---- phase 2: mask + 2-pass softmax ----
    const int lob = 64 - t0;
    const int hib = 1087 - t0;
#pragma unroll
    for (int i = 0; i < 4; ++i) {
        int row = lm * 4 + i;
        int lo = max(row, lob), hi = min(row + 128, hib);
        float m = -1e30f;
#pragma unroll
        for (int j = 0; j < 5; ++j) {
            int cc = colb + j;
            if (cc < lo || cc > hi) acc[i][j] = -1e30f;
            m = fmaxf(m, acc[i][j]);
        }
        red[row * 33 + wid * 4 + ln] = m;
    }
    __syncthreads();
    if (tid < AR) {
        float m = red[tid * 33];
#pragma unroll
        for (int p = 1; p < 32; ++p) m = fmaxf(m, red[tid * 33 + p]);
        rmax[tid] = m;
    }
    __syncthreads();

    float* Ps = Ks;    // K region dead; safe: all warps passed the sync above
#pragma unroll
    for (int i = 0; i < 4; ++i) {
        int row = lm * 4 + i;
        float m = rmax[row];
        float s = 0.f;
        float* pd = Ps + row * APS + colb;
#pragma unroll
        for (int j = 0; j < 5; ++j) {
            float e = __expf(acc[i][j] - m);
            s += e;
            pd[j] = e;
        }
        red[row * 33 + wid * 4 + ln] = s;
    }
    __syncthreads();
    if (tid < AR) {
        float s = 0.f;
#pragma unroll
        for (int p = 0; p < 32; ++p) s += red[tid * 33 + p];
        rinv[tid] = 1.0f / s;
    }
    __syncthreads();

    // ---- phase 3: out = P @ V ----
    const int prow = (wid << 2) + (lane >> 3);   // 1 row per thread
    const int pcol = (lane & 7) * 8;             // 8 dh cols per thread
    float pv[8];
#pragma unroll
    for (int j = 0; j < 8; ++j) pv[j] = 0.f;

    const float* Pp = Ps + prow * APS;
    const float* Vp = Vs + pcol;
#pragma unroll 4
    for (int k = 0; k < AU; ++k) {
        float p = Pp[k];
        float4 v0 = *(const float4*)(Vp + k * AVS);
        float4 v1 = *(const float4*)(Vp + k * AVS + 4);
        pv[0] += p * v0.x; pv[1] += p * v0.y;
        pv[2] += p * v0.z; pv[3] += p * v0.w;
        pv[4] += p * v1.x; pv[5] += p * v1.y;
        pv[6] += p * v1.z; pv[7] += p * v1.w;
    }

    const float inv = rinv[prow];
    float* op = g_attn + base + (size_t)(t0 + prow) * DD + pcol;
    float4 o0, o1;
    o0.x = to_tf32(pv[0] * inv); o0.y = to_tf32(pv[1] * inv);
    o0.z = to_tf32(pv[2] * inv); o0.w = to_tf32(pv[3] * inv);
    o1.x = to_tf32(pv[4] * inv); o1.y = to_tf32(pv[5] * inv);
    o1.z = to_tf32(pv[6] * inv); o1.w = to_tf32(pv[7] * inv);
    *(float4*)(op + 0) = o0;
    *(float4*)(op + 4) = o1;
}

// ---------------- launch ----------------
extern "C" void kernel_launch(void* const* d_in, const int* in_sizes, int n_in,
                              void* d_out, int out_size)
{
    const float* x  = (const float*)d_in[0];
    const float* wq = (const float*)d_in[1];
    const float* bq = (const float*)d_in[2];
    const float* wk = (const float*)d_in[3];
    const float* bk = (const float*)d_in[4];
    const float* wv = (const float*)d_in[5];
    const float* bv = (const float*)d_in[6];
    const float* wo = (const float*)d_in[7];
    const float* bo = (const float*)d_in[8];

    cudaFuncSetAttribute(gemm_qkv_tc,
                         cudaFuncAttributeMaxDynamicSharedMemorySize, SMEM_BYTES);
    cudaFuncSetAttribute(gemm_out_tc,
                         cudaFuncAttributeMaxDynamicSharedMemorySize, SMEM_BYTES);
    cudaFuncSetAttribute(attn_tile_kernel,
                         cudaFuncAttributeMaxDynamicSharedMemorySize, ATT_SMEM_BYTES);

    preconv_kernel<<<6144, 256>>>(x, wq, wk, wv, wo);

    dim3 gq(GN / BN, GM / BM, 3);
    gemm_qkv_tc<<<gq, 256, SMEM_BYTES>>>(bq, bk, bv);

    attn_tile_kernel<<<dim3(TT / AR, NB * HH), 256, ATT_SMEM_BYTES>>>();

    dim3 go(GN / BN, GM / BM);
    gemm_out_tc<<<go, 256, SMEM_BYTES>>>(bo, (float*)d_out);
}

// round 10
// speedup vs baseline: 1.1517x; 1.1493x over previous
#include <cuda_runtime.h>
#include <math.h>
#include <stdint.h>

// Problem constants
#define NB   2
#define TT   1024
#define DD   1024
#define HH   16
#define DHH  64
#define WW   64
#define WIN  129

// GEMM dims
#define GM 2048
#define GN 1024
#define GK 1024
// Tiling
#define BM 128
#define BN 128
#define BK 32
#define SROW 36
#define NITER (GK / BK)
#define SMEM_FLOATS (2 * 2 * BM * SROW)      // 2 buffers x (A+B) x 128 x 36
#define SMEM_BYTES  (SMEM_FLOATS * 4)        // 73728

// Attention tiling: CTA = 32 t-rows, window union 160
#define AR   32
#define AU   160
#define AQS  66
#define AKS  66
#define AVS  68
#define APS  164
#define SM_Q   0
#define SM_K   2112
#define SM_V   12672
#define SM_RED 23552          // [32][33]
#define SM_MAX 24608
#define SM_INV 24640
#define ATT_SMEM_BYTES (24672 * 4)   // 98688

// Scratch (device globals: allocation-free per harness rules)
__device__ float g_q[NB * TT * DD];
__device__ float g_k[NB * TT * DD];
__device__ float g_v[NB * TT * DD];
__device__ float g_attn[NB * TT * DD];

__device__ __forceinline__ float to_tf32(float x) {
    float r;
    asm("cvt.rna.tf32.f32 %0, %1;" : "=f"(r) : "f"(x));
    return r;
}

__device__ __forceinline__ void mma_16x8x8_tf32(float* d, const uint32_t* a,
                                                const uint32_t* b) {
    asm volatile(
        "mma.sync.aligned.m16n8k8.row.col.f32.tf32.tf32.f32 "
        "{%0,%1,%2,%3}, {%4,%5,%6,%7}, {%8,%9}, {%0,%1,%2,%3};"
        : "+f"(d[0]), "+f"(d[1]), "+f"(d[2]), "+f"(d[3])
        : "r"(a[0]), "r"(a[1]), "r"(a[2]), "r"(a[3]),
          "r"(b[0]), "r"(b[1]));
}

// ---------------------------------------------------------------------------
// tf32 mma.sync GEMM: C[M,N] = A[M,K] @ B[N,K]^T + bias  (R6 version, verbatim:
// register-staged double buffer, inline tf32 cvt, 110.9us measured on QKV)
// ---------------------------------------------------------------------------
__device__ __forceinline__ void gemm_tc_body(
    const float* __restrict__ A, const float* __restrict__ B,
    const float* __restrict__ bias, float* __restrict__ C)
{
    extern __shared__ float smem[];
    float* Asm = smem;
    float* Bsm = smem + 2 * BM * SROW;

    const int tid  = threadIdx.x;
    const int lane = tid & 31;
    const int wid  = tid >> 5;
    const int wm   = wid >> 2;
    const int wn   = wid & 3;
    const int row0 = blockIdx.y * BM;
    const int col0 = blockIdx.x * BN;

    const int lrow = tid >> 3;
    const int lq   = tid & 7;

    float acc[4][4][4];
#pragma unroll
    for (int m = 0; m < 4; ++m)
#pragma unroll
        for (int n = 0; n < 4; ++n)
#pragma unroll
            for (int e = 0; e < 4; ++e) acc[m][n][e] = 0.f;

    float4 pa[4], pb[4];

#pragma unroll
    for (int p = 0; p < 4; ++p) {
        int r = p * 32 + lrow;
        pa[p] = *(const float4*)(A + (size_t)(row0 + r) * GK + lq * 4);
        pb[p] = *(const float4*)(B + (size_t)(col0 + r) * GK + lq * 4);
    }
#pragma unroll
    for (int p = 0; p < 4; ++p) {
        int r = p * 32 + lrow;
        float4 va = pa[p], vb = pb[p];
        va.x = to_tf32(va.x); va.y = to_tf32(va.y);
        va.z = to_tf32(va.z); va.w = to_tf32(va.w);
        vb.x = to_tf32(vb.x); vb.y = to_tf32(vb.y);
        vb.z = to_tf32(vb.z); vb.w = to_tf32(vb.w);
        *(float4*)(Asm + r * SROW + lq * 4) = va;
        *(float4*)(Bsm + r * SROW + lq * 4) = vb;
    }
    __syncthreads();

    const int c  = lane & 3;
    const int r4 = lane >> 2;

    for (int i = 0; i < NITER; ++i) {
        const int buf = i & 1;
        const float* Ab = Asm + buf * (BM * SROW);
        const float* Bb = Bsm + buf * (BM * SROW);

        if (i + 1 < NITER) {
            const int k0 = (i + 1) * BK;
#pragma unroll
            for (int p = 0; p < 4; ++p) {
                int r = p * 32 + lrow;
                pa[p] = *(const float4*)(A + (size_t)(row0 + r) * GK + k0 + lq * 4);
                pb[p] = *(const float4*)(B + (size_t)(col0 + r) * GK + k0 + lq * 4);
            }
        }

        const uint32_t* Au = (const uint32_t*)(Ab + (wm * 64 + r4) * SROW + c);
        const uint32_t* Bu = (const uint32_t*)(Bb + (wn * 32 + r4) * SROW + c);

#pragma unroll
        for (int kk = 0; kk < 4; ++kk) {
            uint32_t af[4][4], bf[4][2];
            const int ko = kk * 8;
#pragma unroll
            for (int m = 0; m < 4; ++m) {
                af[m][0] = Au[(m * 16 + 0) * SROW + ko + 0];
                af[m][1] = Au[(m * 16 + 8) * SROW + ko + 0];
                af[m][2] = Au[(m * 16 + 0) * SROW + ko + 4];
                af[m][3] = Au[(m * 16 + 8) * SROW + ko + 4];
            }
#pragma unroll
            for (int n = 0; n < 4; ++n) {
                bf[n][0] = Bu[n * 8 * SROW + ko + 0];
                bf[n][1] = Bu[n * 8 * SROW + ko + 4];
            }
#pragma unroll
            for (int m = 0; m < 4; ++m)
#pragma unroll
                for (int n = 0; n < 4; ++n)
                    mma_16x8x8_tf32(acc[m][n], af[m], bf[n]);
        }

        if (i + 1 < NITER) {
            float* Aw = Asm + (buf ^ 1) * (BM * SROW);
            float* Bw = Bsm + (buf ^ 1) * (BM * SROW);
#pragma unroll
            for (int p = 0; p < 4; ++p) {
                int r = p * 32 + lrow;
                float4 va = pa[p], vb = pb[p];
                va.x = to_tf32(va.x); va.y = to_tf32(va.y);
                va.z = to_tf32(va.z); va.w = to_tf32(va.w);
                vb.x = to_tf32(vb.x); vb.y = to_tf32(vb.y);
                vb.z = to_tf32(vb.z); vb.w = to_tf32(vb.w);
                *(float4*)(Aw + r * SROW + lq * 4) = va;
                *(float4*)(Bw + r * SROW + lq * 4) = vb;
            }
            __syncthreads();
        }
    }

#pragma unroll
    for (int m = 0; m < 4; ++m) {
#pragma unroll
        for (int h = 0; h < 2; ++h) {
            const int grow = row0 + wm * 64 + m * 16 + r4 + 8 * h;
            float* crow = C + (size_t)grow * GN;
#pragma unroll
            for (int n = 0; n < 4; ++n) {
                const int gcol = col0 + wn * 32 + n * 8 + 2 * c;
                float2 o;
                o.x = acc[m][n][2 * h + 0] + __ldg(&bias[gcol + 0]);
                o.y = acc[m][n][2 * h + 1] + __ldg(&bias[gcol + 1]);
                *(float2*)(crow + gcol) = o;
            }
        }
    }
}

__global__ __launch_bounds__(256, 2) void gemm_qkv_tc(
    const float* __restrict__ x,
    const float* __restrict__ wq, const float* __restrict__ bq,
    const float* __restrict__ wk, const float* __restrict__ bk,
    const float* __restrict__ wv, const float* __restrict__ bv)
{
    const float* B; const float* bias; float* C;
    if (blockIdx.z == 0)      { B = wq; bias = bq; C = g_q; }
    else if (blockIdx.z == 1) { B = wk; bias = bk; C = g_k; }
    else                      { B = wv; bias = bv; C = g_v; }
    gemm_tc_body(x, B, bias, C);
}

__global__ __launch_bounds__(256, 2) void gemm_out_tc(
    const float* __restrict__ wo, const float* __restrict__ bo,
    float* __restrict__ out)
{
    gemm_tc_body(g_attn, wo, bo, out);
}

// ---------------------------------------------------------------------------
// Tiled windowed attention (fp32). CTA = 32 t-rows; union 160 positions.
// smem: Q[32][66] | K[160][66] (reused as P[32][164]) | V[160][68] | red[32][33]
// Phase 3 remapped: 2 rows x 4 dh per thread -> V loads broadcast across rows,
// V traffic amortized; FFMA-bound instead of LDS-bound.
// ---------------------------------------------------------------------------
__global__ __launch_bounds__(256) void attn_tile_kernel()
{
    extern __shared__ float sm[];
    float* Qs   = sm + SM_Q;
    float* Ks   = sm + SM_K;
    float* Vs   = sm + SM_V;
    float* red  = sm + SM_RED;
    float* rmax = sm + SM_MAX;
    float* rinv = sm + SM_INV;

    const int tid = threadIdx.x;
    const int t0  = blockIdx.x * AR;
    const int nh  = blockIdx.y;
    const int h   = nh & (HH - 1);
    const int n   = nh >> 4;
    const size_t base = (size_t)n * TT * DD + (size_t)h * DHH;

    // ---- loads ----
    for (int idx = tid; idx < AR * 16; idx += 256) {
        int r = idx >> 4, cc = (idx & 15) << 2;
        float4 v = *(const float4*)(g_q + base + (size_t)(t0 + r) * DD + cc);
        float* dst = Qs + r * AQS + cc;
        ((float2*)dst)[0] = make_float2(v.x * 0.125f, v.y * 0.125f);
        ((float2*)dst)[1] = make_float2(v.z * 0.125f, v.w * 0.125f);
    }
    for (int idx = tid; idx < AU * 16; idx += 256) {
        int r = idx >> 4, cc = (idx & 15) << 2;
        int pos = min(max(t0 - 64 + r, 0), TT - 1);
        float4 kv = *(const float4*)(g_k + base + (size_t)pos * DD + cc);
        float* kd = Ks + r * AKS + cc;
        ((float2*)kd)[0] = make_float2(kv.x, kv.y);
        ((float2*)kd)[1] = make_float2(kv.z, kv.w);
        float4 vv = *(const float4*)(g_v + base + (size_t)pos * DD + cc);
        *(float4*)(Vs + r * AVS + cc) = vv;
    }
    __syncthreads();

    const int lane = tid & 31, wid = tid >> 5;
    const int lm = lane >> 2, ln = lane & 3;     // lanes 8(M) x 4(N)
    const int colb = wid * 20 + ln * 5;          // 5 cols per thread

    // ---- phase 1: S = Q @ K^T  (rows lm*4+i, cols colb+j) ----
    float acc[4][5];
#pragma unroll
    for (int i = 0; i < 4; ++i)
#pragma unroll
        for (int j = 0; j < 5; ++j) acc[i][j] = 0.f;

    const float* Qp = Qs + (lm * 4) * AQS;
    const float* Kp = Ks + colb * AKS;
    for (int k2 = 0; k2 < 32; ++k2) {
        float2 a[4], b[5];
#pragma unroll
        for (int i = 0; i < 4; ++i)
            a[i] = *(const float2*)(Qp + i * AQS + 2 * k2);
#pragma unroll
        for (int j = 0; j < 5; ++j)
            b[j] = *(const float2*)(Kp + j * AKS + 2 * k2);
#pragma unroll
        for (int i = 0; i < 4; ++i)
#pragma unroll
            for (int j = 0; j < 5; ++j)
                acc[i][j] += a[i].x * b[j].x + a[i].y * b[j].y;
    }

    // ---- phase 2: mask + 2-pass softmax ----
    const int lob = 64 - t0;
    const int hib = 1087 - t0;
#pragma unroll
    for (int i = 0; i < 4; ++i) {
        int row = lm * 4 + i;
        int lo = max(row, lob), hi = min(row + 128, hib);
        float m = -1e30f;
#pragma unroll
        for (int j = 0; j < 5; ++j) {
            int cc = colb + j;
            if (cc < lo || cc > hi) acc[i][j] = -1e30f;
            m = fmaxf(m, acc[i][j]);
        }
        red[row * 33 + wid * 4 + ln] = m;
    }
    __syncthreads();
    if (tid < AR) {
        float m = red[tid * 33];
#pragma unroll
        for (int p = 1; p < 32; ++p) m = fmaxf(m, red[tid * 33 + p]);
        rmax[tid] = m;
    }
    __syncthreads();

    float* Ps = Ks;    // K region dead; safe: all warps passed the sync above
#pragma unroll
    for (int i = 0; i < 4; ++i) {
        int row = lm * 4 + i;
        float m = rmax[row];
        float s = 0.f;
        float* pd = Ps + row * APS + colb;
#pragma unroll
        for (int j = 0; j < 5; ++j) {
            float e = __expf(acc[i][j] - m);
            s += e;
            pd[j] = e;
        }
        red[row * 33 + wid * 4 + ln] = s;
    }
    __syncthreads();
    if (tid < AR) {
        float s = 0.f;
#pragma unroll
        for (int p = 0; p < 32; ++p) s += red[tid * 33 + p];
        rinv[tid] = 1.0f / s;
    }
    __syncthreads();

    // ---- phase 3: out = P @ V  (2 rows x 4 dh per thread) ----
    const int dhg  = tid & 15;          // 16 dh-groups of 4
    const int rowg = tid >> 4;          // 16 row-groups of 2
    const int pcol = dhg * 4;
    const int r0p  = rowg * 2;

    float pv0[4] = {0.f, 0.f, 0.f, 0.f};
    float pv1[4] = {0.f, 0.f, 0.f, 0.f};

    const float* P0 = Ps + (r0p + 0) * APS;
    const float* P1 = Ps + (r0p + 1) * APS;
    const float* Vp = Vs + pcol;

#pragma unroll 2
    for (int k = 0; k < AU; k += 2) {
        float2 p0 = *(const float2*)(P0 + k);     // broadcast across 16 threads
        float2 p1 = *(const float2*)(P1 + k);
        float4 v0 = *(const float4*)(Vp + (k + 0) * AVS);
        float4 v1 = *(const float4*)(Vp + (k + 1) * AVS);
        pv0[0] += p0.x * v0.x + p0.y * v1.x;
        pv0[1] += p0.x * v0.y + p0.y * v1.y;
        pv0[2] += p0.x * v0.z + p0.y * v1.z;
        pv0[3] += p0.x * v0.w + p0.y * v1.w;
        pv1[0] += p1.x * v0.x + p1.y * v1.x;
        pv1[1] += p1.x * v0.y + p1.y * v1.y;
        pv1[2] += p1.x * v0.z + p1.y * v1.z;
        pv1[3] += p1.x * v0.w + p1.y * v1.w;
    }

    const float i0 = rinv[r0p + 0];
    const float i1 = rinv[r0p + 1];
    float* o0 = g_attn + base + (size_t)(t0 + r0p + 0) * DD + pcol;
    float* o1 = g_attn + base + (size_t)(t0 + r0p + 1) * DD + pcol;
    *(float4*)o0 = make_float4(pv0[0] * i0, pv0[1] * i0, pv0[2] * i0, pv0[3] * i0);
    *(float4*)o1 = make_float4(pv1[0] * i1, pv1[1] * i1, pv1[2] * i1, pv1[3] * i1);
}

// ---------------- launch ----------------
extern "C" void kernel_launch(void* const* d_in, const int* in_sizes, int n_in,
                              void* d_out, int out_size)
{
    const float* x  = (const float*)d_in[0];
    const float* wq = (const float*)d_in[1];
    const float* bq = (const float*)d_in[2];
    const float* wk = (const float*)d_in[3];
    const float* bk = (const float*)d_in[4];
    const float* wv = (const float*)d_in[5];
    const float* bv = (const float*)d_in[6];
    const float* wo = (const float*)d_in[7];
    const float* bo = (const float*)d_in[8];

    cudaFuncSetAttribute(gemm_qkv_tc,
                         cudaFuncAttributeMaxDynamicSharedMemorySize, SMEM_BYTES);
    cudaFuncSetAttribute(gemm_out_tc,
                         cudaFuncAttributeMaxDynamicSharedMemorySize, SMEM_BYTES);
    cudaFuncSetAttribute(attn_tile_kernel,
                         cudaFuncAttributeMaxDynamicSharedMemorySize, ATT_SMEM_BYTES);

    dim3 gq(GN / BN, GM / BM, 3);
    gemm_qkv_tc<<<gq, 256, SMEM_BYTES>>>(x, wq, bq, wk, bk, wv, bv);

    attn_tile_kernel<<<dim3(TT / AR, NB * HH), 256, ATT_SMEM_BYTES>>>();

    dim3 go(GN / BN, GM / BM);
    gemm_out_tc<<<go, 256, SMEM_BYTES>>>(wo, bo, (float*)d_out);
}